// round 14
// baseline (speedup 1.0000x reference)
#include <cuda_runtime.h>
#include <cuda_fp16.h>
#include <cstdint>

// ==================== problem constants ====================
constexpr int Dh  = 128;
constexpr int SQ  = 2048;
constexpr int SKV = 2048;
constexpr int NB  = 8;
constexpr int BM  = 128;        // q rows per CTA
constexpr int BN  = 64;         // keys per tile
constexpr int NT  = SKV / BN;   // 32
constexpr int NTHREADS = 256;

// smem: padded 272B row stride (256B data + 16B) -> conflict-free ldmatrix
constexpr int RSTRIDE = 272;
constexpr int SM_QH  = 0;
constexpr int SM_QL  = SM_QH + BM * RSTRIDE;     // 34816
constexpr int SM_STG = SM_QL + BM * RSTRIDE;     // 69632
constexpr int PLANE  = BN * RSTRIDE;             // 17408
constexpr int STG_SZ = 3 * PLANE;                // 52224 (Khi, Klo, Vh)
constexpr int NSTG   = 3;                        // triple-buffered ring
constexpr int SMEM_TOTAL = SM_STG + NSTG * STG_SZ;  // 226304 (< 227KB cap)

// ==================== device scratch (fp16 planes) ====================
__device__ __half g_Qh[NB * SQ * Dh];
__device__ __half g_Ql[NB * SQ * Dh];
__device__ __half g_Kh[NB * SKV * Dh];
__device__ __half g_Kl[NB * SKV * Dh];
__device__ __half g_Vh[NB * SKV * Dh];

// ==================== helpers ====================
__device__ __forceinline__ uint32_t smem_u32(const void* p) {
    uint32_t a;
    asm("{ .reg .u64 t; cvta.to.shared.u64 t, %1; cvt.u32.u64 %0, t; }"
        : "=r"(a) : "l"(p));
    return a;
}

__device__ __forceinline__ uint32_t pack2h(float lo, float hi) {
    __half2 h = __floats2half2_rn(lo, hi);
    return *reinterpret_cast<uint32_t*>(&h);
}

__device__ __forceinline__ void splitwh(float a, float b, uint32_t& hw, uint32_t& lw) {
    float ha = __half2float(__float2half_rn(a));
    float hb = __half2float(__float2half_rn(b));
    hw = pack2h(ha, hb);
    lw = pack2h(a - ha, b - hb);
}

// mma m16n8k16 fp16 -> fp32 accum
__device__ __forceinline__ void mma16816(float d[4], const uint32_t a[4], const uint32_t b[2]) {
    asm volatile(
        "mma.sync.aligned.m16n8k16.row.col.f32.f16.f16.f32 "
        "{%0,%1,%2,%3}, {%4,%5,%6,%7}, {%8,%9}, {%0,%1,%2,%3};"
        : "+f"(d[0]), "+f"(d[1]), "+f"(d[2]), "+f"(d[3])
        : "r"(a[0]), "r"(a[1]), "r"(a[2]), "r"(a[3]), "r"(b[0]), "r"(b[1]));
}

__device__ __forceinline__ void ldsm_x4(uint32_t r[4], uint32_t addr) {
    asm volatile("ldmatrix.sync.aligned.m8n8.x4.shared.b16 {%0,%1,%2,%3}, [%4];"
        : "=r"(r[0]), "=r"(r[1]), "=r"(r[2]), "=r"(r[3]) : "r"(addr));
}

__device__ __forceinline__ void ldsm_x4t(uint32_t r[4], uint32_t addr) {
    asm volatile("ldmatrix.sync.aligned.m8n8.x4.trans.shared.b16 {%0,%1,%2,%3}, [%4];"
        : "=r"(r[0]), "=r"(r[1]), "=r"(r[2]), "=r"(r[3]) : "r"(addr));
}

__device__ __forceinline__ void cpa16(uint32_t dst, const void* src) {
    asm volatile("cp.async.cg.shared.global [%0], [%1], 16;" :: "r"(dst), "l"(src));
}
#define CP_COMMIT() asm volatile("cp.async.commit_group;" ::: "memory")
#define CP_WAIT1()  asm volatile("cp.async.wait_group 1;" ::: "memory")

__device__ __forceinline__ void load_plane(uint32_t dst, const __half* src, int tid) {
    #pragma unroll
    for (int i = 0; i < 4; i++) {
        int c = tid + NTHREADS * i;          // 0..1023
        int row = c >> 4, col = c & 15;
        cpa16(dst + row * RSTRIDE + col * 16, src + row * Dh + col * 8);
    }
}

__device__ __forceinline__ void load_stage(uint32_t sb, int slot, int bb, int jt, int tid) {
    uint32_t base = sb + SM_STG + slot * STG_SZ;
    size_t g = ((size_t)bb * SKV + (size_t)jt * BN) * Dh;
    load_plane(base + 0 * PLANE, g_Kh + g, tid);
    load_plane(base + 1 * PLANE, g_Kl + g, tid);
    load_plane(base + 2 * PLANE, g_Vh + g, tid);
}

// load one QK b-fragment set: {b0H, b1H, b0L, b1L} for key-group pair jjp at k-slice sp
__device__ __forceinline__ void ld_bset(uint32_t b[16], uint32_t stg, uint32_t kaddr0,
                                        int jjp, int sp) {
    uint32_t ka = stg + kaddr0 + (uint32_t)((2 * jjp) * 8 * RSTRIDE + sp * 64);
    ldsm_x4(b + 0,  ka);
    ldsm_x4(b + 4,  ka + 8 * RSTRIDE);
    ldsm_x4(b + 8,  ka + PLANE);
    ldsm_x4(b + 12, ka + 8 * RSTRIDE + PLANE);
}

// ==================== prep kernel: fp32 -> fp16 hi/lo planes ====================
__global__ void __launch_bounds__(NTHREADS)
prep_kernel(const float4* __restrict__ x1, const float4* __restrict__ x2,
            const float4* __restrict__ x3)
{
    int t = blockIdx.y;
    const float4* src = (t == 0) ? x1 : (t == 1) ? x2 : x3;
    __half* dh = (t == 0) ? g_Qh : (t == 1) ? g_Kh : g_Vh;
    __half* dl = (t == 0) ? g_Ql : g_Kl;     // unused for t==2
    int i = blockIdx.x * NTHREADS + threadIdx.x;
    float4 v = src[i];
    uint32_t h0, l0, h1, l1;
    splitwh(v.x, v.y, h0, l0);
    splitwh(v.z, v.w, h1, l1);
    *reinterpret_cast<uint2*>(dh + (size_t)i * 4) = make_uint2(h0, h1);
    if (t < 2)
        *reinterpret_cast<uint2*>(dl + (size_t)i * 4) = make_uint2(l0, l1);
}

// ==================== main kernel ====================
__global__ void __launch_bounds__(NTHREADS, 1)
attn_main(const float* __restrict__ mask, float* __restrict__ out)
{
    extern __shared__ char smem[];
    const uint32_t sb = smem_u32(smem);
    const int tid  = threadIdx.x;
    const int w    = tid >> 5;      // warp: q rows 16w..16w+15
    const int lane = tid & 31;
    const int qc   = lane & 3;
    const int qr   = lane >> 2;
    const int bb   = blockIdx.x >> 4;
    const int qt   = blockIdx.x & 15;

    // ---- prologue: Q + stage0 (group 0), stage1 (group 1) ----
    {
        size_t qbase = ((size_t)bb * SQ + (size_t)qt * BM) * Dh;
        #pragma unroll
        for (int i = 0; i < 8; i++) {
            int c = tid + NTHREADS * i;
            int row = c >> 4, col = c & 15;
            cpa16(sb + SM_QH + row * RSTRIDE + col * 16, g_Qh + qbase + row * Dh + col * 8);
            cpa16(sb + SM_QL + row * RSTRIDE + col * 16, g_Ql + qbase + row * Dh + col * 8);
        }
        load_stage(sb, 0, bb, 0, tid);
        CP_COMMIT();
        load_stage(sb, 1, bb, 1, tid);
        CP_COMMIT();
    }

    float oacc[16][4] = {};
    float lac0 = 0.f, lac1 = 0.f;
    float m0r = -1e30f, m1r = -1e30f;   // running row maxima

    const int row_g = qt * BM + 16 * w + qr;
    const float* mk0 = mask + ((size_t)bb * SQ + row_g) * SKV;
    const float* mk1 = mk0 + (size_t)8 * SKV;

    const uint32_t qaddrH = sb + SM_QH + (16 * w + (lane & 15)) * RSTRIDE + (lane >> 4) * 16;
    const uint32_t qaddrL = qaddrH + (uint32_t)(SM_QL - SM_QH);
    const uint32_t kaddr0 = (uint32_t)((lane & 7) * RSTRIDE + ((lane >> 3) & 3) * 16);

    int s_cur = 0;    // ring slot holding tile j

    #pragma unroll 1
    for (int j = 0; j < NT; j++) {
        CP_WAIT1();            // group for tile j complete (j+1 may remain in flight)
        __syncthreads();       // all warps: slot s_cur visible; slot (s_cur+2)%3 fully consumed

        // ---- issue loads for tile j+2 into the just-freed slot (no bottom barrier) ----
        if (j + 2 < NT) load_stage(sb, (s_cur + 2) % NSTG, bb, j + 2, tid);
        CP_COMMIT();           // always commit to keep wait_group counts aligned

        // ---- mask prefetch (latency hides under QK MMAs) ----
        float2 mreg[8][2];
        #pragma unroll
        for (int jj = 0; jj < 8; jj++) {
            mreg[jj][0] = *reinterpret_cast<const float2*>(mk0 + (size_t)j * BN + jj * 8 + 2 * qc);
            mreg[jj][1] = *reinterpret_cast<const float2*>(mk1 + (size_t)j * BN + jj * 8 + 2 * qc);
        }

        const uint32_t stg = sb + SM_STG + (uint32_t)s_cur * STG_SZ;
        s_cur = (s_cur + 1) % NSTG;

        // ---- QK: 3-pass fp16 emulation, b-fragments software-pipelined ----
        float sacc[8][4] = {};
        uint32_t bA[16], bB[16];
        ld_bset(bA, stg, kaddr0, 0, 0);
        #pragma unroll
        for (int sp = 0; sp < 4; sp++) {
            uint32_t aH0[4], aH1[4], aL0[4], aL1[4];
            ldsm_x4(aH0, qaddrH + sp * 64);
            ldsm_x4(aH1, qaddrH + sp * 64 + 32);
            ldsm_x4(aL0, qaddrL + sp * 64);
            ldsm_x4(aL1, qaddrL + sp * 64 + 32);
            #pragma unroll
            for (int jjp = 0; jjp < 4; jjp++) {
                uint32_t* cur = ((sp * 4 + jjp) & 1) ? bB : bA;
                uint32_t* nxt = ((sp * 4 + jjp) & 1) ? bA : bB;
                // prefetch next b-set: its ~35cyc latency hides under the 12 MMAs below
                if (!(sp == 3 && jjp == 3)) {
                    int njjp = (jjp + 1) & 3;
                    int nsp  = (jjp == 3) ? sp + 1 : sp;
                    ld_bset(nxt, stg, kaddr0, njjp, nsp);
                }
                float* s0 = sacc[2 * jjp];
                float* s1 = sacc[2 * jjp + 1];
                // hi*hi
                mma16816(s0, aH0, cur + 0);   mma16816(s1, aH0, cur + 4);
                mma16816(s0, aH1, cur + 2);   mma16816(s1, aH1, cur + 6);
                // cross terms (fp32 accum)
                mma16816(s0, aL0, cur + 0);   mma16816(s1, aL0, cur + 4);
                mma16816(s0, aH0, cur + 8);   mma16816(s1, aH0, cur + 12);
                mma16816(s0, aL1, cur + 2);   mma16816(s1, aL1, cur + 6);
                mma16816(s0, aH1, cur + 10);  mma16816(s1, aH1, cur + 14);
            }
        }

        // ---- online softmax: p = exp(s - m_running) in (0,1] -> fp16-safe ----
        float tmax0 = -1e30f, tmax1 = -1e30f;
        #pragma unroll
        for (int jj = 0; jj < 8; jj++) {
            tmax0 = fmaxf(tmax0, fmaxf(sacc[jj][0], sacc[jj][1]));
            tmax1 = fmaxf(tmax1, fmaxf(sacc[jj][2], sacc[jj][3]));
        }
        tmax0 = fmaxf(tmax0, __shfl_xor_sync(0xffffffffu, tmax0, 1));
        tmax0 = fmaxf(tmax0, __shfl_xor_sync(0xffffffffu, tmax0, 2));
        tmax1 = fmaxf(tmax1, __shfl_xor_sync(0xffffffffu, tmax1, 1));
        tmax1 = fmaxf(tmax1, __shfl_xor_sync(0xffffffffu, tmax1, 2));
        float nm0 = fmaxf(m0r, tmax0);
        float nm1 = fmaxf(m1r, tmax1);
        float alpha0 = __expf(m0r - nm0);
        float alpha1 = __expf(m1r - nm1);
        m0r = nm0; m1r = nm1;
        // skip O-rescale when every row's max is unchanged (common after warmup)
        if (!__all_sync(0xffffffffu, (alpha0 == 1.f) & (alpha1 == 1.f))) {
            lac0 *= alpha0;
            lac1 *= alpha1;
            #pragma unroll
            for (int j2 = 0; j2 < 16; j2++) {
                oacc[j2][0] *= alpha0; oacc[j2][1] *= alpha0;
                oacc[j2][2] *= alpha1; oacc[j2][3] *= alpha1;
            }
        }

        uint32_t ph[8][2];
        #pragma unroll
        for (int jj = 0; jj < 8; jj++) {
            float p0 = __expf(sacc[jj][0] - nm0);
            float p1 = __expf(sacc[jj][1] - nm0);
            float p2 = __expf(sacc[jj][2] - nm1);
            float p3 = __expf(sacc[jj][3] - nm1);
            lac0 += p0 + p1;
            lac1 += p2 + p3;
            p0 *= mreg[jj][0].x; p1 *= mreg[jj][0].y;
            p2 *= mreg[jj][1].x; p3 *= mreg[jj][1].y;
            ph[jj][0] = pack2h(p0, p1);
            ph[jj][1] = pack2h(p2, p3);
        }

        // ---- PV: single-pass fp16, pair-interleaved dv accumulators ----
        #pragma unroll
        for (int kkp = 0; kkp < 2; kkp++) {
            uint32_t aH0[4] = { ph[4*kkp  ][0], ph[4*kkp  ][1], ph[4*kkp+1][0], ph[4*kkp+1][1] };
            uint32_t aH1[4] = { ph[4*kkp+2][0], ph[4*kkp+2][1], ph[4*kkp+3][0], ph[4*kkp+3][1] };
            #pragma unroll
            for (int j2p = 0; j2p < 8; j2p++) {
                const int ja = 2 * j2p, jb = 2 * j2p + 1;
                uint32_t bHa[4], bHb[4];
                uint32_t va = stg + 2 * PLANE + (32 * kkp + lane) * RSTRIDE + ja * 16;
                ldsm_x4t(bHa, va);
                ldsm_x4t(bHb, va + 16);
                mma16816(oacc[ja], aH0, &bHa[0]);  mma16816(oacc[jb], aH0, &bHb[0]);
                mma16816(oacc[ja], aH1, &bHa[2]);  mma16816(oacc[jb], aH1, &bHb[2]);
            }
        }
        // no bottom barrier: the top barrier of tile j+1 protects slot reuse
    }

    // ---- finalize: reduce l within quads (maxima already quad-uniform) ----
    lac0 += __shfl_xor_sync(0xffffffffu, lac0, 1);
    lac0 += __shfl_xor_sync(0xffffffffu, lac0, 2);
    lac1 += __shfl_xor_sync(0xffffffffu, lac1, 1);
    lac1 += __shfl_xor_sync(0xffffffffu, lac1, 2);
    float inv0 = 1.0f / lac0;
    float inv1 = 1.0f / lac1;

    float* o0 = out + ((size_t)bb * SQ + row_g) * Dh;
    float* o1 = o0 + (size_t)8 * Dh;
    #pragma unroll
    for (int j2 = 0; j2 < 16; j2++) {
        *reinterpret_cast<float2*>(o0 + j2 * 8 + 2 * qc) =
            make_float2(oacc[j2][0] * inv0, oacc[j2][1] * inv0);
        *reinterpret_cast<float2*>(o1 + j2 * 8 + 2 * qc) =
            make_float2(oacc[j2][2] * inv1, oacc[j2][3] * inv1);
    }
}

// ==================== launch ====================
extern "C" void kernel_launch(void* const* d_in, const int* in_sizes, int n_in,
                              void* d_out, int out_size) {
    const float* x1   = (const float*)d_in[0];
    const float* x2   = (const float*)d_in[1];
    const float* x3   = (const float*)d_in[2];
    const float* mask = (const float*)d_in[3];
    float* out = (float*)d_out;

    dim3 pgrid(NB * SQ * Dh / 4 / NTHREADS, 3);
    prep_kernel<<<pgrid, NTHREADS>>>(
        (const float4*)x1, (const float4*)x2, (const float4*)x3);

    cudaFuncSetAttribute(attn_main,
                         cudaFuncAttributeMaxDynamicSharedMemorySize, SMEM_TOTAL);
    attn_main<<<128, NTHREADS, SMEM_TOTAL>>>(mask, out);
}

// round 15
// speedup vs baseline: 1.0156x; 1.0156x over previous
#include <cuda_runtime.h>
#include <cuda_fp16.h>
#include <cstdint>

// ==================== problem constants ====================
constexpr int Dh  = 128;
constexpr int SQ  = 2048;
constexpr int SKV = 2048;
constexpr int NB  = 8;
constexpr int BM  = 128;        // q rows per CTA
constexpr int BN  = 64;         // keys per tile
constexpr int NT  = SKV / BN;   // 32
constexpr int NTHREADS = 256;

// smem: padded 272B row stride (256B data + 16B) -> conflict-free ldmatrix
constexpr int RSTRIDE = 272;
constexpr int SM_QH  = 0;
constexpr int SM_QL  = SM_QH + BM * RSTRIDE;     // 34816
constexpr int SM_STG = SM_QL + BM * RSTRIDE;     // 69632
constexpr int PLANE  = BN * RSTRIDE;             // 17408
constexpr int STG_SZ = 3 * PLANE;                // 52224 (Khi, Klo, Vh)
constexpr int SMEM_TOTAL = SM_STG + 2 * STG_SZ;  // 174080

// ==================== device scratch (fp16 planes; Q handled in-kernel) ====================
__device__ __half g_Kh[NB * SKV * Dh];
__device__ __half g_Kl[NB * SKV * Dh];
__device__ __half g_Vh[NB * SKV * Dh];

// ==================== helpers ====================
__device__ __forceinline__ uint32_t smem_u32(const void* p) {
    uint32_t a;
    asm("{ .reg .u64 t; cvta.to.shared.u64 t, %1; cvt.u32.u64 %0, t; }"
        : "=r"(a) : "l"(p));
    return a;
}

__device__ __forceinline__ uint32_t pack2h(float lo, float hi) {
    __half2 h = __floats2half2_rn(lo, hi);
    return *reinterpret_cast<uint32_t*>(&h);
}

__device__ __forceinline__ void splitwh(float a, float b, uint32_t& hw, uint32_t& lw) {
    float ha = __half2float(__float2half_rn(a));
    float hb = __half2float(__float2half_rn(b));
    hw = pack2h(ha, hb);
    lw = pack2h(a - ha, b - hb);
}

// mma m16n8k16 fp16 -> fp32 accum
__device__ __forceinline__ void mma16816(float d[4], const uint32_t a[4], const uint32_t b[2]) {
    asm volatile(
        "mma.sync.aligned.m16n8k16.row.col.f32.f16.f16.f32 "
        "{%0,%1,%2,%3}, {%4,%5,%6,%7}, {%8,%9}, {%0,%1,%2,%3};"
        : "+f"(d[0]), "+f"(d[1]), "+f"(d[2]), "+f"(d[3])
        : "r"(a[0]), "r"(a[1]), "r"(a[2]), "r"(a[3]), "r"(b[0]), "r"(b[1]));
}

__device__ __forceinline__ void ldsm_x4(uint32_t r[4], uint32_t addr) {
    asm volatile("ldmatrix.sync.aligned.m8n8.x4.shared.b16 {%0,%1,%2,%3}, [%4];"
        : "=r"(r[0]), "=r"(r[1]), "=r"(r[2]), "=r"(r[3]) : "r"(addr));
}

__device__ __forceinline__ void ldsm_x4t(uint32_t r[4], uint32_t addr) {
    asm volatile("ldmatrix.sync.aligned.m8n8.x4.trans.shared.b16 {%0,%1,%2,%3}, [%4];"
        : "=r"(r[0]), "=r"(r[1]), "=r"(r[2]), "=r"(r[3]) : "r"(addr));
}

__device__ __forceinline__ void cpa16(uint32_t dst, const void* src) {
    asm volatile("cp.async.cg.shared.global [%0], [%1], 16;" :: "r"(dst), "l"(src));
}
#define CP_COMMIT() asm volatile("cp.async.commit_group;" ::: "memory")
#define CP_WAIT1()  asm volatile("cp.async.wait_group 1;" ::: "memory")

__device__ __forceinline__ void load_plane(uint32_t dst, const __half* src, int tid) {
    #pragma unroll
    for (int i = 0; i < 4; i++) {
        int c = tid + NTHREADS * i;          // 0..1023
        int row = c >> 4, col = c & 15;
        cpa16(dst + row * RSTRIDE + col * 16, src + row * Dh + col * 8);
    }
}

__device__ __forceinline__ void load_stage(uint32_t sb, int stg, int bb, int jt, int tid) {
    uint32_t base = sb + SM_STG + stg * STG_SZ;
    size_t g = ((size_t)bb * SKV + (size_t)jt * BN) * Dh;
    load_plane(base + 0 * PLANE, g_Kh + g, tid);
    load_plane(base + 1 * PLANE, g_Kl + g, tid);
    load_plane(base + 2 * PLANE, g_Vh + g, tid);
}

// load one QK b-fragment set: {b0H, b1H, b0L, b1L} for key-group pair jjp at k-slice sp
__device__ __forceinline__ void ld_bset(uint32_t b[16], uint32_t stg, uint32_t kaddr0,
                                        int jjp, int sp) {
    uint32_t ka = stg + kaddr0 + (uint32_t)((2 * jjp) * 8 * RSTRIDE + sp * 64);
    ldsm_x4(b + 0,  ka);
    ldsm_x4(b + 4,  ka + 8 * RSTRIDE);
    ldsm_x4(b + 8,  ka + PLANE);
    ldsm_x4(b + 12, ka + 8 * RSTRIDE + PLANE);
}

// ==================== prep kernel: K -> fp16 hi/lo, V -> fp16 ====================
__global__ void __launch_bounds__(NTHREADS)
prep_kernel(const float4* __restrict__ x2, const float4* __restrict__ x3)
{
    int t = blockIdx.y;
    const float4* src = (t == 0) ? x2 : x3;
    __half* dh = (t == 0) ? g_Kh : g_Vh;
    int i = blockIdx.x * NTHREADS + threadIdx.x;
    float4 v = src[i];
    uint32_t h0, l0, h1, l1;
    splitwh(v.x, v.y, h0, l0);
    splitwh(v.z, v.w, h1, l1);
    *reinterpret_cast<uint2*>(dh + (size_t)i * 4) = make_uint2(h0, h1);
    if (t == 0)
        *reinterpret_cast<uint2*>(g_Kl + (size_t)i * 4) = make_uint2(l0, l1);
}

// ==================== main kernel ====================
__global__ void __launch_bounds__(NTHREADS, 1)
attn_main(const float* __restrict__ x1, const float* __restrict__ mask,
          float* __restrict__ out)
{
    extern __shared__ char smem[];
    const uint32_t sb = smem_u32(smem);
    const int tid  = threadIdx.x;
    const int w    = tid >> 5;      // warp: q rows 16w..16w+15
    const int lane = tid & 31;
    const int qc   = lane & 3;
    const int qr   = lane >> 2;
    const int bb   = blockIdx.x >> 4;
    const int qt   = blockIdx.x & 15;

    // ---- prologue: stage0/1 via cp.async; Q split in-kernel (fp32 -> hi/lo smem) ----
    {
        load_stage(sb, 0, bb, 0, tid);
        CP_COMMIT();
        load_stage(sb, 1, bb, 1, tid);
        CP_COMMIT();

        const float4* q4 = reinterpret_cast<const float4*>(
            x1 + ((size_t)bb * SQ + (size_t)qt * BM) * Dh);
        #pragma unroll
        for (int i = 0; i < 16; i++) {
            int c = tid + NTHREADS * i;      // 0..4095 float4s (32 per row)
            int row = c >> 5;
            int col4 = c & 31;
            float4 v = q4[c];
            uint32_t h0, l0, h1, l1;
            splitwh(v.x, v.y, h0, l0);
            splitwh(v.z, v.w, h1, l1);
            *reinterpret_cast<uint2*>(smem + SM_QH + row * RSTRIDE + col4 * 8) = make_uint2(h0, h1);
            *reinterpret_cast<uint2*>(smem + SM_QL + row * RSTRIDE + col4 * 8) = make_uint2(l0, l1);
        }
    }

    float oacc[16][4] = {};
    float lac0 = 0.f, lac1 = 0.f;
    float m0r = -1e30f, m1r = -1e30f;   // running row maxima

    const int row_g = qt * BM + 16 * w + qr;
    const float* mk0 = mask + ((size_t)bb * SQ + row_g) * SKV;
    const float* mk1 = mk0 + (size_t)8 * SKV;

    const uint32_t qaddrH = sb + SM_QH + (16 * w + (lane & 15)) * RSTRIDE + (lane >> 4) * 16;
    const uint32_t qaddrL = qaddrH + (uint32_t)(SM_QL - SM_QH);
    const uint32_t kaddr0 = (uint32_t)((lane & 7) * RSTRIDE + ((lane >> 3) & 3) * 16);

    #pragma unroll 1
    for (int j = 0; j < NT; j++) {
        CP_WAIT1();
        __syncthreads();   // stage (j&1) + (j==0: Q smem) visible to all warps

        // ---- mask prefetch (latency hides under QK MMAs) ----
        float2 mreg[8][2];
        #pragma unroll
        for (int jj = 0; jj < 8; jj++) {
            mreg[jj][0] = *reinterpret_cast<const float2*>(mk0 + (size_t)j * BN + jj * 8 + 2 * qc);
            mreg[jj][1] = *reinterpret_cast<const float2*>(mk1 + (size_t)j * BN + jj * 8 + 2 * qc);
        }

        const uint32_t stg = sb + SM_STG + (uint32_t)(j & 1) * STG_SZ;

        // ---- QK: 3-pass fp16 emulation, b-fragments software-pipelined ----
        float sacc[8][4] = {};
        uint32_t bA[16], bB[16];
        ld_bset(bA, stg, kaddr0, 0, 0);
        #pragma unroll
        for (int sp = 0; sp < 4; sp++) {
            uint32_t aH0[4], aH1[4], aL0[4], aL1[4];
            ldsm_x4(aH0, qaddrH + sp * 64);
            ldsm_x4(aH1, qaddrH + sp * 64 + 32);
            ldsm_x4(aL0, qaddrL + sp * 64);
            ldsm_x4(aL1, qaddrL + sp * 64 + 32);
            #pragma unroll
            for (int jjp = 0; jjp < 4; jjp++) {
                uint32_t* cur = ((sp * 4 + jjp) & 1) ? bB : bA;
                uint32_t* nxt = ((sp * 4 + jjp) & 1) ? bA : bB;
                // prefetch next b-set: its ~35cyc latency hides under the 12 MMAs below
                if (!(sp == 3 && jjp == 3)) {
                    int njjp = (jjp + 1) & 3;
                    int nsp  = (jjp == 3) ? sp + 1 : sp;
                    ld_bset(nxt, stg, kaddr0, njjp, nsp);
                }
                float* s0 = sacc[2 * jjp];
                float* s1 = sacc[2 * jjp + 1];
                // hi*hi
                mma16816(s0, aH0, cur + 0);   mma16816(s1, aH0, cur + 4);
                mma16816(s0, aH1, cur + 2);   mma16816(s1, aH1, cur + 6);
                // cross terms (fp32 accum)
                mma16816(s0, aL0, cur + 0);   mma16816(s1, aL0, cur + 4);
                mma16816(s0, aH0, cur + 8);   mma16816(s1, aH0, cur + 12);
                mma16816(s0, aL1, cur + 2);   mma16816(s1, aL1, cur + 6);
                mma16816(s0, aH1, cur + 10);  mma16816(s1, aH1, cur + 14);
            }
        }

        // ---- online softmax: p = exp(s - m_running) in (0,1] -> fp16-safe ----
        float tmax0 = -1e30f, tmax1 = -1e30f;
        #pragma unroll
        for (int jj = 0; jj < 8; jj++) {
            tmax0 = fmaxf(tmax0, fmaxf(sacc[jj][0], sacc[jj][1]));
            tmax1 = fmaxf(tmax1, fmaxf(sacc[jj][2], sacc[jj][3]));
        }
        tmax0 = fmaxf(tmax0, __shfl_xor_sync(0xffffffffu, tmax0, 1));
        tmax0 = fmaxf(tmax0, __shfl_xor_sync(0xffffffffu, tmax0, 2));
        tmax1 = fmaxf(tmax1, __shfl_xor_sync(0xffffffffu, tmax1, 1));
        tmax1 = fmaxf(tmax1, __shfl_xor_sync(0xffffffffu, tmax1, 2));
        float nm0 = fmaxf(m0r, tmax0);
        float nm1 = fmaxf(m1r, tmax1);
        float alpha0 = __expf(m0r - nm0);
        float alpha1 = __expf(m1r - nm1);
        m0r = nm0; m1r = nm1;
        // skip O-rescale when every row's max is unchanged (common after warmup)
        if (!__all_sync(0xffffffffu, (alpha0 == 1.f) & (alpha1 == 1.f))) {
            lac0 *= alpha0;
            lac1 *= alpha1;
            #pragma unroll
            for (int j2 = 0; j2 < 16; j2++) {
                oacc[j2][0] *= alpha0; oacc[j2][1] *= alpha0;
                oacc[j2][2] *= alpha1; oacc[j2][3] *= alpha1;
            }
        }

        uint32_t ph[8][2];
        #pragma unroll
        for (int jj = 0; jj < 8; jj++) {
            float p0 = __expf(sacc[jj][0] - nm0);
            float p1 = __expf(sacc[jj][1] - nm0);
            float p2 = __expf(sacc[jj][2] - nm1);
            float p3 = __expf(sacc[jj][3] - nm1);
            lac0 += p0 + p1;
            lac1 += p2 + p3;
            p0 *= mreg[jj][0].x; p1 *= mreg[jj][0].y;
            p2 *= mreg[jj][1].x; p3 *= mreg[jj][1].y;
            ph[jj][0] = pack2h(p0, p1);
            ph[jj][1] = pack2h(p2, p3);
        }

        // ---- PV: single-pass fp16, pair-interleaved dv accumulators ----
        #pragma unroll
        for (int kkp = 0; kkp < 2; kkp++) {
            uint32_t aH0[4] = { ph[4*kkp  ][0], ph[4*kkp  ][1], ph[4*kkp+1][0], ph[4*kkp+1][1] };
            uint32_t aH1[4] = { ph[4*kkp+2][0], ph[4*kkp+2][1], ph[4*kkp+3][0], ph[4*kkp+3][1] };
            #pragma unroll
            for (int j2p = 0; j2p < 8; j2p++) {
                const int ja = 2 * j2p, jb = 2 * j2p + 1;
                uint32_t bHa[4], bHb[4];
                uint32_t va = stg + 2 * PLANE + (32 * kkp + lane) * RSTRIDE + ja * 16;
                ldsm_x4t(bHa, va);
                ldsm_x4t(bHb, va + 16);
                mma16816(oacc[ja], aH0, &bHa[0]);  mma16816(oacc[jb], aH0, &bHb[0]);
                mma16816(oacc[ja], aH1, &bHa[2]);  mma16816(oacc[jb], aH1, &bHb[2]);
            }
        }

        __syncthreads();
        if (j + 2 < NT) load_stage(sb, j & 1, bb, j + 2, tid);
        CP_COMMIT();
    }

    // ---- finalize: reduce l within quads (maxima already quad-uniform) ----
    lac0 += __shfl_xor_sync(0xffffffffu, lac0, 1);
    lac0 += __shfl_xor_sync(0xffffffffu, lac0, 2);
    lac1 += __shfl_xor_sync(0xffffffffu, lac1, 1);
    lac1 += __shfl_xor_sync(0xffffffffu, lac1, 2);
    float inv0 = 1.0f / lac0;
    float inv1 = 1.0f / lac1;

    float* o0 = out + ((size_t)bb * SQ + row_g) * Dh;
    float* o1 = o0 + (size_t)8 * Dh;
    #pragma unroll
    for (int j2 = 0; j2 < 16; j2++) {
        *reinterpret_cast<float2*>(o0 + j2 * 8 + 2 * qc) =
            make_float2(oacc[j2][0] * inv0, oacc[j2][1] * inv0);
        *reinterpret_cast<float2*>(o1 + j2 * 8 + 2 * qc) =
            make_float2(oacc[j2][2] * inv1, oacc[j2][3] * inv1);
    }
}

// ==================== launch ====================
extern "C" void kernel_launch(void* const* d_in, const int* in_sizes, int n_in,
                              void* d_out, int out_size) {
    const float* x1   = (const float*)d_in[0];
    const float* x2   = (const float*)d_in[1];
    const float* x3   = (const float*)d_in[2];
    const float* mask = (const float*)d_in[3];
    float* out = (float*)d_out;

    dim3 pgrid(NB * SKV * Dh / 4 / NTHREADS, 2);   // (2048, 2): K hi/lo, V
    prep_kernel<<<pgrid, NTHREADS>>>((const float4*)x2, (const float4*)x3);

    cudaFuncSetAttribute(attn_main,
                         cudaFuncAttributeMaxDynamicSharedMemorySize, SMEM_TOTAL);
    attn_main<<<128, NTHREADS, SMEM_TOTAL>>>(x1, mask, out);
}

// round 16
// speedup vs baseline: 1.0453x; 1.0292x over previous
#include <cuda_runtime.h>
#include <cuda_fp16.h>
#include <cstdint>

// ==================== problem constants ====================
constexpr int Dh  = 128;
constexpr int SQ  = 2048;
constexpr int SKV = 2048;
constexpr int NB  = 8;
constexpr int BM  = 128;        // q rows per CTA
constexpr int BN  = 64;         // keys per tile
constexpr int NT  = SKV / BN;   // 32
constexpr int NTHREADS = 256;

// smem: padded 272B row stride (256B data + 16B) -> conflict-free ldmatrix
constexpr int RSTRIDE = 272;
constexpr int SM_QH  = 0;
constexpr int SM_QL  = SM_QH + BM * RSTRIDE;     // 34816
constexpr int SM_STG = SM_QL + BM * RSTRIDE;     // 69632
constexpr int PLANE  = BN * RSTRIDE;             // 17408
constexpr int STG_SZ = 3 * PLANE;                // 52224 (Khi, Klo, Vh)
constexpr int SMEM_TOTAL = SM_STG + 2 * STG_SZ;  // 174080

// ==================== device scratch (fp16 planes) ====================
__device__ __half g_Qh[NB * SQ * Dh];
__device__ __half g_Ql[NB * SQ * Dh];
__device__ __half g_Kh[NB * SKV * Dh];
__device__ __half g_Kl[NB * SKV * Dh];
__device__ __half g_Vh[NB * SKV * Dh];

// ==================== helpers ====================
__device__ __forceinline__ uint32_t smem_u32(const void* p) {
    uint32_t a;
    asm("{ .reg .u64 t; cvta.to.shared.u64 t, %1; cvt.u32.u64 %0, t; }"
        : "=r"(a) : "l"(p));
    return a;
}

__device__ __forceinline__ uint32_t pack2h(float lo, float hi) {
    __half2 h = __floats2half2_rn(lo, hi);
    return *reinterpret_cast<uint32_t*>(&h);
}

__device__ __forceinline__ void splitwh(float a, float b, uint32_t& hw, uint32_t& lw) {
    float ha = __half2float(__float2half_rn(a));
    float hb = __half2float(__float2half_rn(b));
    hw = pack2h(ha, hb);
    lw = pack2h(a - ha, b - hb);
}

// mma m16n8k16 fp16 -> fp32 accum
__device__ __forceinline__ void mma16816(float d[4], const uint32_t a[4], const uint32_t b[2]) {
    asm volatile(
        "mma.sync.aligned.m16n8k16.row.col.f32.f16.f16.f32 "
        "{%0,%1,%2,%3}, {%4,%5,%6,%7}, {%8,%9}, {%0,%1,%2,%3};"
        : "+f"(d[0]), "+f"(d[1]), "+f"(d[2]), "+f"(d[3])
        : "r"(a[0]), "r"(a[1]), "r"(a[2]), "r"(a[3]), "r"(b[0]), "r"(b[1]));
}

__device__ __forceinline__ void ldsm_x4(uint32_t r[4], uint32_t addr) {
    asm volatile("ldmatrix.sync.aligned.m8n8.x4.shared.b16 {%0,%1,%2,%3}, [%4];"
        : "=r"(r[0]), "=r"(r[1]), "=r"(r[2]), "=r"(r[3]) : "r"(addr));
}

__device__ __forceinline__ void ldsm_x4t(uint32_t r[4], uint32_t addr) {
    asm volatile("ldmatrix.sync.aligned.m8n8.x4.trans.shared.b16 {%0,%1,%2,%3}, [%4];"
        : "=r"(r[0]), "=r"(r[1]), "=r"(r[2]), "=r"(r[3]) : "r"(addr));
}

__device__ __forceinline__ void cpa16(uint32_t dst, const void* src) {
    asm volatile("cp.async.cg.shared.global [%0], [%1], 16;" :: "r"(dst), "l"(src));
}
#define CP_COMMIT() asm volatile("cp.async.commit_group;" ::: "memory")
#define CP_WAIT1()  asm volatile("cp.async.wait_group 1;" ::: "memory")

__device__ __forceinline__ void load_plane(uint32_t dst, const __half* src, int tid) {
    #pragma unroll
    for (int i = 0; i < 4; i++) {
        int c = tid + NTHREADS * i;          // 0..1023
        int row = c >> 4, col = c & 15;
        cpa16(dst + row * RSTRIDE + col * 16, src + row * Dh + col * 8);
    }
}

__device__ __forceinline__ void load_stage(uint32_t sb, int stg, int bb, int jt, int tid) {
    uint32_t base = sb + SM_STG + stg * STG_SZ;
    size_t g = ((size_t)bb * SKV + (size_t)jt * BN) * Dh;
    load_plane(base + 0 * PLANE, g_Kh + g, tid);
    load_plane(base + 1 * PLANE, g_Kl + g, tid);
    load_plane(base + 2 * PLANE, g_Vh + g, tid);
}

// load one QK b-fragment set: {b0H, b1H, b0L, b1L} for key-group pair jjp at k-slice sp
__device__ __forceinline__ void ld_bset(uint32_t b[16], uint32_t stg, uint32_t kaddr0,
                                        int jjp, int sp) {
    uint32_t ka = stg + kaddr0 + (uint32_t)((2 * jjp) * 8 * RSTRIDE + sp * 64);
    ldsm_x4(b + 0,  ka);
    ldsm_x4(b + 4,  ka + 8 * RSTRIDE);
    ldsm_x4(b + 8,  ka + PLANE);
    ldsm_x4(b + 12, ka + 8 * RSTRIDE + PLANE);
}

// ==================== prep kernel: fp32 -> fp16 hi/lo planes ====================
// 2 float4 per thread -> one 16B hi store + one 16B lo store (full-width STG.128)
__global__ void __launch_bounds__(NTHREADS)
prep_kernel(const float4* __restrict__ x1, const float4* __restrict__ x2,
            const float4* __restrict__ x3)
{
    int t = blockIdx.y;
    const float4* src = (t == 0) ? x1 : (t == 1) ? x2 : x3;
    __half* dh = (t == 0) ? g_Qh : (t == 1) ? g_Kh : g_Vh;
    __half* dl = (t == 0) ? g_Ql : g_Kl;     // unused for t==2
    int i = blockIdx.x * NTHREADS + threadIdx.x;   // pair index
    float4 v0 = src[2 * i];
    float4 v1 = src[2 * i + 1];
    uint4 hq, lq;
    splitwh(v0.x, v0.y, hq.x, lq.x);
    splitwh(v0.z, v0.w, hq.y, lq.y);
    splitwh(v1.x, v1.y, hq.z, lq.z);
    splitwh(v1.z, v1.w, hq.w, lq.w);
    *reinterpret_cast<uint4*>(dh + (size_t)i * 8) = hq;
    if (t < 2)
        *reinterpret_cast<uint4*>(dl + (size_t)i * 8) = lq;
}

// ==================== main kernel (byte-identical to R10) ====================
__global__ void __launch_bounds__(NTHREADS, 1)
attn_main(const float* __restrict__ mask, float* __restrict__ out)
{
    extern __shared__ char smem[];
    const uint32_t sb = smem_u32(smem);
    const int tid  = threadIdx.x;
    const int w    = tid >> 5;      // warp: q rows 16w..16w+15
    const int lane = tid & 31;
    const int qc   = lane & 3;
    const int qr   = lane >> 2;
    const int bb   = blockIdx.x >> 4;
    const int qt   = blockIdx.x & 15;

    // ---- prologue: Q + stage0, stage1 ----
    {
        size_t qbase = ((size_t)bb * SQ + (size_t)qt * BM) * Dh;
        #pragma unroll
        for (int i = 0; i < 8; i++) {
            int c = tid + NTHREADS * i;
            int row = c >> 4, col = c & 15;
            cpa16(sb + SM_QH + row * RSTRIDE + col * 16, g_Qh + qbase + row * Dh + col * 8);
            cpa16(sb + SM_QL + row * RSTRIDE + col * 16, g_Ql + qbase + row * Dh + col * 8);
        }
        load_stage(sb, 0, bb, 0, tid);
        CP_COMMIT();
        load_stage(sb, 1, bb, 1, tid);
        CP_COMMIT();
    }

    float oacc[16][4] = {};
    float lac0 = 0.f, lac1 = 0.f;
    float m0r = -1e30f, m1r = -1e30f;   // running row maxima

    const int row_g = qt * BM + 16 * w + qr;
    const float* mk0 = mask + ((size_t)bb * SQ + row_g) * SKV;
    const float* mk1 = mk0 + (size_t)8 * SKV;

    const uint32_t qaddrH = sb + SM_QH + (16 * w + (lane & 15)) * RSTRIDE + (lane >> 4) * 16;
    const uint32_t qaddrL = qaddrH + (uint32_t)(SM_QL - SM_QH);
    const uint32_t kaddr0 = (uint32_t)((lane & 7) * RSTRIDE + ((lane >> 3) & 3) * 16);

    #pragma unroll 1
    for (int j = 0; j < NT; j++) {
        CP_WAIT1();
        __syncthreads();

        // ---- mask prefetch (latency hides under QK MMAs) ----
        float2 mreg[8][2];
        #pragma unroll
        for (int jj = 0; jj < 8; jj++) {
            mreg[jj][0] = *reinterpret_cast<const float2*>(mk0 + (size_t)j * BN + jj * 8 + 2 * qc);
            mreg[jj][1] = *reinterpret_cast<const float2*>(mk1 + (size_t)j * BN + jj * 8 + 2 * qc);
        }

        const uint32_t stg = sb + SM_STG + (uint32_t)(j & 1) * STG_SZ;

        // ---- QK: 3-pass fp16 emulation, b-fragments software-pipelined ----
        float sacc[8][4] = {};
        uint32_t bA[16], bB[16];
        ld_bset(bA, stg, kaddr0, 0, 0);
        #pragma unroll
        for (int sp = 0; sp < 4; sp++) {
            uint32_t aH0[4], aH1[4], aL0[4], aL1[4];
            ldsm_x4(aH0, qaddrH + sp * 64);
            ldsm_x4(aH1, qaddrH + sp * 64 + 32);
            ldsm_x4(aL0, qaddrL + sp * 64);
            ldsm_x4(aL1, qaddrL + sp * 64 + 32);
            #pragma unroll
            for (int jjp = 0; jjp < 4; jjp++) {
                uint32_t* cur = ((sp * 4 + jjp) & 1) ? bB : bA;
                uint32_t* nxt = ((sp * 4 + jjp) & 1) ? bA : bB;
                // prefetch next b-set: its ~35cyc latency hides under the 12 MMAs below
                if (!(sp == 3 && jjp == 3)) {
                    int njjp = (jjp + 1) & 3;
                    int nsp  = (jjp == 3) ? sp + 1 : sp;
                    ld_bset(nxt, stg, kaddr0, njjp, nsp);
                }
                float* s0 = sacc[2 * jjp];
                float* s1 = sacc[2 * jjp + 1];
                // hi*hi
                mma16816(s0, aH0, cur + 0);   mma16816(s1, aH0, cur + 4);
                mma16816(s0, aH1, cur + 2);   mma16816(s1, aH1, cur + 6);
                // cross terms (fp32 accum)
                mma16816(s0, aL0, cur + 0);   mma16816(s1, aL0, cur + 4);
                mma16816(s0, aH0, cur + 8);   mma16816(s1, aH0, cur + 12);
                mma16816(s0, aL1, cur + 2);   mma16816(s1, aL1, cur + 6);
                mma16816(s0, aH1, cur + 10);  mma16816(s1, aH1, cur + 14);
            }
        }

        // ---- online softmax: p = exp(s - m_running) in (0,1] -> fp16-safe ----
        float tmax0 = -1e30f, tmax1 = -1e30f;
        #pragma unroll
        for (int jj = 0; jj < 8; jj++) {
            tmax0 = fmaxf(tmax0, fmaxf(sacc[jj][0], sacc[jj][1]));
            tmax1 = fmaxf(tmax1, fmaxf(sacc[jj][2], sacc[jj][3]));
        }
        tmax0 = fmaxf(tmax0, __shfl_xor_sync(0xffffffffu, tmax0, 1));
        tmax0 = fmaxf(tmax0, __shfl_xor_sync(0xffffffffu, tmax0, 2));
        tmax1 = fmaxf(tmax1, __shfl_xor_sync(0xffffffffu, tmax1, 1));
        tmax1 = fmaxf(tmax1, __shfl_xor_sync(0xffffffffu, tmax1, 2));
        float nm0 = fmaxf(m0r, tmax0);
        float nm1 = fmaxf(m1r, tmax1);
        float alpha0 = __expf(m0r - nm0);
        float alpha1 = __expf(m1r - nm1);
        m0r = nm0; m1r = nm1;
        // skip O-rescale when every row's max is unchanged (common after warmup)
        if (!__all_sync(0xffffffffu, (alpha0 == 1.f) & (alpha1 == 1.f))) {
            lac0 *= alpha0;
            lac1 *= alpha1;
            #pragma unroll
            for (int j2 = 0; j2 < 16; j2++) {
                oacc[j2][0] *= alpha0; oacc[j2][1] *= alpha0;
                oacc[j2][2] *= alpha1; oacc[j2][3] *= alpha1;
            }
        }

        uint32_t ph[8][2];
        #pragma unroll
        for (int jj = 0; jj < 8; jj++) {
            float p0 = __expf(sacc[jj][0] - nm0);
            float p1 = __expf(sacc[jj][1] - nm0);
            float p2 = __expf(sacc[jj][2] - nm1);
            float p3 = __expf(sacc[jj][3] - nm1);
            lac0 += p0 + p1;
            lac1 += p2 + p3;
            p0 *= mreg[jj][0].x; p1 *= mreg[jj][0].y;
            p2 *= mreg[jj][1].x; p3 *= mreg[jj][1].y;
            ph[jj][0] = pack2h(p0, p1);
            ph[jj][1] = pack2h(p2, p3);
        }

        // ---- PV: single-pass fp16, pair-interleaved dv accumulators ----
        #pragma unroll
        for (int kkp = 0; kkp < 2; kkp++) {
            uint32_t aH0[4] = { ph[4*kkp  ][0], ph[4*kkp  ][1], ph[4*kkp+1][0], ph[4*kkp+1][1] };
            uint32_t aH1[4] = { ph[4*kkp+2][0], ph[4*kkp+2][1], ph[4*kkp+3][0], ph[4*kkp+3][1] };
            #pragma unroll
            for (int j2p = 0; j2p < 8; j2p++) {
                const int ja = 2 * j2p, jb = 2 * j2p + 1;
                uint32_t bHa[4], bHb[4];
                uint32_t va = stg + 2 * PLANE + (32 * kkp + lane) * RSTRIDE + ja * 16;
                ldsm_x4t(bHa, va);
                ldsm_x4t(bHb, va + 16);
                mma16816(oacc[ja], aH0, &bHa[0]);  mma16816(oacc[jb], aH0, &bHb[0]);
                mma16816(oacc[ja], aH1, &bHa[2]);  mma16816(oacc[jb], aH1, &bHb[2]);
            }
        }

        __syncthreads();
        if (j + 2 < NT) load_stage(sb, j & 1, bb, j + 2, tid);
        CP_COMMIT();
    }

    // ---- finalize: reduce l within quads (maxima already quad-uniform) ----
    lac0 += __shfl_xor_sync(0xffffffffu, lac0, 1);
    lac0 += __shfl_xor_sync(0xffffffffu, lac0, 2);
    lac1 += __shfl_xor_sync(0xffffffffu, lac1, 1);
    lac1 += __shfl_xor_sync(0xffffffffu, lac1, 2);
    float inv0 = 1.0f / lac0;
    float inv1 = 1.0f / lac1;

    float* o0 = out + ((size_t)bb * SQ + row_g) * Dh;
    float* o1 = o0 + (size_t)8 * Dh;
    #pragma unroll
    for (int j2 = 0; j2 < 16; j2++) {
        *reinterpret_cast<float2*>(o0 + j2 * 8 + 2 * qc) =
            make_float2(oacc[j2][0] * inv0, oacc[j2][1] * inv0);
        *reinterpret_cast<float2*>(o1 + j2 * 8 + 2 * qc) =
            make_float2(oacc[j2][2] * inv1, oacc[j2][3] * inv1);
    }
}

// ==================== launch ====================
extern "C" void kernel_launch(void* const* d_in, const int* in_sizes, int n_in,
                              void* d_out, int out_size) {
    const float* x1   = (const float*)d_in[0];
    const float* x2   = (const float*)d_in[1];
    const float* x3   = (const float*)d_in[2];
    const float* mask = (const float*)d_in[3];
    float* out = (float*)d_out;

    dim3 pgrid(NB * SQ * Dh / 8 / NTHREADS, 3);   // (1024, 3): 2 float4 per thread
    prep_kernel<<<pgrid, NTHREADS>>>(
        (const float4*)x1, (const float4*)x2, (const float4*)x3);

    cudaFuncSetAttribute(attn_main,
                         cudaFuncAttributeMaxDynamicSharedMemorySize, SMEM_TOTAL);
    attn_main<<<128, NTHREADS, SMEM_TOTAL>>>(mask, out);
}